// round 15
// baseline (speedup 1.0000x reference)
#include <cuda_runtime.h>
#include <cuda_bf16.h>
#include <cfloat>
#include <cstdint>

// Problem constants
#define NVERT 10242
#define DLEV  4
#define DIM   256
#define HEADS 8
#define HD    32
#define KNBR  8
#define MTOK  (NVERT * DLEV)          // 40968 tokens
#define KSPLIT 768                    // split-bf16 K: A=[hi|lo|hi] . B=[hi|hi|lo]
#define QSCALE 5.65685424949238f      // sqrt(32)

// Scratch (device globals; no allocation allowed)
__device__ float          g_qkv[(size_t)MTOK * 3 * DIM];     // [M,768] f32: q|k|v
__device__ __nv_bfloat16  g_xbf[(size_t)MTOK * KSPLIT];      // x split  [hi|lo|hi]
__device__ __nv_bfloat16  g_ybf[(size_t)MTOK * KSPLIT];      // y split  [hi|lo|hi]
__device__ __nv_bfloat16  g_wqkv[(size_t)(3*DIM) * KSPLIT];  // qkv_w split [hi|hi|lo]
__device__ __nv_bfloat16  g_wproj[(size_t)DIM * KSPLIT];     // proj_w split [hi|hi|lo]

// ===========================================================================
// helpers
// ===========================================================================
__device__ __forceinline__ uint32_t smem_u32(const void* p) {
    uint32_t a;
    asm("{ .reg .u64 t; cvta.to.shared.u64 t, %1; cvt.u32.u64 %0, t; }" : "=r"(a) : "l"(p));
    return a;
}
__device__ __forceinline__ void cp_async16(uint32_t saddr, const void* gptr, uint32_t bytes) {
    asm volatile("cp.async.cg.shared.global [%0], [%1], 16, %2;\n"
                 :: "r"(saddr), "l"(gptr), "r"(bytes));
}
__device__ __forceinline__ void cp_commit() {
    asm volatile("cp.async.commit_group;\n" ::: "memory");
}
template <int N>
__device__ __forceinline__ void cp_wait() {
    asm volatile("cp.async.wait_group %0;\n" :: "n"(N) : "memory");
}
__device__ __forceinline__ void ldsm_x4(uint32_t& r0, uint32_t& r1, uint32_t& r2, uint32_t& r3,
                                        uint32_t addr) {
    asm volatile("ldmatrix.sync.aligned.m8n8.x4.shared.b16 {%0,%1,%2,%3}, [%4];"
                 : "=r"(r0), "=r"(r1), "=r"(r2), "=r"(r3) : "r"(addr));
}
__device__ __forceinline__ void mma16816(float* d, const uint32_t* a, const uint32_t* b) {
    asm volatile(
        "mma.sync.aligned.m16n8k16.row.col.f32.bf16.bf16.f32 "
        "{%0,%1,%2,%3}, {%4,%5,%6,%7}, {%8,%9}, {%0,%1,%2,%3};"
        : "+f"(d[0]), "+f"(d[1]), "+f"(d[2]), "+f"(d[3])
        : "r"(a[0]), "r"(a[1]), "r"(a[2]), "r"(a[3]), "r"(b[0]), "r"(b[1]));
}

// ===========================================================================
// bf16 tensor-core GEMM (round-8 proven): 128x128 CTA tile, BK=64,
// 8 warps (2x4) of 64x32 warp tiles, cp.async double-buffered,
// XOR-swizzled smem, fused bias (+q scale).
// ===========================================================================
#define BK 64
#define KITERS (KSPLIT / BK)       // 12
#define TILE_BYTES (128 * BK * 2)  // 16384
#define BUF_BYTES  (2 * TILE_BYTES)
#define GEMM_SMEM  (2 * BUF_BYTES) // 65536

template <bool SCALEQ>
__global__ __launch_bounds__(256, 2)
void gemm_mma(const __nv_bfloat16* __restrict__ A, const __nv_bfloat16* __restrict__ B,
              const float* __restrict__ bias, float* __restrict__ C, int M, int N)
{
    extern __shared__ char sm[];
    const uint32_t smb = smem_u32(sm);
    const int tid  = threadIdx.x;
    const int lane = tid & 31;
    const int w    = tid >> 5;
    const int wm   = w >> 2;           // 0..1
    const int wn   = w & 3;            // 0..3
    const int bm   = blockIdx.y * 128;
    const int bn   = blockIdx.x * 128;

    const int a_r0  = wm * 64 + ((lane >> 3) & 1) * 8 + (lane & 7);
    const int a_khi = lane >> 4;
    const int b_r0  = wn * 32 + ((lane >> 4) & 1) * 8 + (lane & 7);
    const int b_khi = (lane >> 3) & 1;

    float acc[4][4][4];
    #pragma unroll
    for (int i = 0; i < 4; i++)
        #pragma unroll
        for (int j = 0; j < 4; j++)
            #pragma unroll
            for (int c = 0; c < 4; c++) acc[i][j][c] = 0.f;

    auto load_tile = [&](int buf, int it) {
        const int k0 = it * BK;
        const uint32_t sA = smb + buf * BUF_BYTES;
        const uint32_t sB = sA + TILE_BYTES;
        #pragma unroll
        for (int i = 0; i < 4; i++) {
            int e = tid + i * 256;
            int r = e >> 3, u = e & 7;
            int gr = bm + r;
            bool ok = gr < M;
            const __nv_bfloat16* ga = A + (size_t)(ok ? gr : 0) * KSPLIT + k0 + u * 8;
            cp_async16(sA + r * 128 + ((u ^ (r & 7)) << 4), ga, ok ? 16u : 0u);
            const __nv_bfloat16* gb = B + (size_t)(bn + r) * KSPLIT + k0 + u * 8;
            cp_async16(sB + r * 128 + ((u ^ (r & 7)) << 4), gb, 16u);
        }
        cp_commit();
    };

    auto compute = [&](int buf) {
        const uint32_t sA = smb + buf * BUF_BYTES;
        const uint32_t sB = sA + TILE_BYTES;
        #pragma unroll
        for (int ks = 0; ks < BK / 16; ks++) {
            uint32_t a[4][4];
            #pragma unroll
            for (int mf = 0; mf < 4; mf++) {
                int row = a_r0 + mf * 16;
                int ku  = ks * 2 + a_khi;
                ldsm_x4(a[mf][0], a[mf][1], a[mf][2], a[mf][3],
                        sA + row * 128 + ((ku ^ (row & 7)) << 4));
            }
            uint32_t b[4][2];
            #pragma unroll
            for (int np = 0; np < 2; np++) {
                int row = b_r0 + np * 16;
                int ku  = ks * 2 + b_khi;
                uint32_t r0, r1, r2, r3;
                ldsm_x4(r0, r1, r2, r3, sB + row * 128 + ((ku ^ (row & 7)) << 4));
                b[np * 2 + 0][0] = r0; b[np * 2 + 0][1] = r1;
                b[np * 2 + 1][0] = r2; b[np * 2 + 1][1] = r3;
            }
            #pragma unroll
            for (int mf = 0; mf < 4; mf++)
                #pragma unroll
                for (int nf = 0; nf < 4; nf++)
                    mma16816(acc[mf][nf], a[mf], b[nf]);
        }
    };

    load_tile(0, 0);
    #pragma unroll 1
    for (int it = 0; it < KITERS; it++) {
        if (it + 1 < KITERS) { load_tile((it + 1) & 1, it + 1); cp_wait<1>(); }
        else                 { cp_wait<0>(); }
        __syncthreads();
        compute(it & 1);
        __syncthreads();
    }

    const int gn_base = bn + wn * 32 + (lane & 3) * 2;
    #pragma unroll
    for (int mf = 0; mf < 4; mf++) {
        #pragma unroll
        for (int half = 0; half < 2; half++) {
            int gm = bm + wm * 64 + mf * 16 + (lane >> 2) + half * 8;
            if (gm >= M) continue;
            #pragma unroll
            for (int nf = 0; nf < 4; nf++) {
                int gn = gn_base + nf * 8;
                float v0 = acc[mf][nf][half * 2 + 0] + bias[gn];
                float v1 = acc[mf][nf][half * 2 + 1] + bias[gn + 1];
                if (SCALEQ && gn < DIM) { v0 *= QSCALE; v1 *= QSCALE; }
                *(float2*)(C + (size_t)gm * N + gn) = make_float2(v0, v1);
            }
        }
    }
}

// ===========================================================================
// Merged fp32 -> split-bf16 conversion for all three tensors in ONE launch.
//   x      (A-side): [hi | lo | hi]   blocks [0, 10242)
//   qkv_w  (B-side): [hi | hi | lo]   blocks [10242, 10434)
//   proj_w (B-side): [hi | hi | lo]   blocks [10434, 10498)
// ===========================================================================
#define XBLKS  (MTOK / 4)            // 10242
#define WQBLKS (3 * DIM / 4)         // 192
#define WPBLKS (DIM / 4)             // 64

__global__ void conv_all(const float* __restrict__ x,
                         const float* __restrict__ wq,
                         const float* __restrict__ wp,
                         __nv_bfloat16* __restrict__ xd,
                         __nv_bfloat16* __restrict__ wqd,
                         __nv_bfloat16* __restrict__ wpd)
{
    int b = blockIdx.x;
    const float* src;
    __nv_bfloat16* dst;
    bool bside;
    int idx;
    if (b < XBLKS)                 { src = x;  dst = xd;  bside = false; idx = b * 256 + threadIdx.x; }
    else if (b < XBLKS + WQBLKS)   { src = wq; dst = wqd; bside = true;  idx = (b - XBLKS) * 256 + threadIdx.x; }
    else                           { src = wp; dst = wpd; bside = true;  idx = (b - XBLKS - WQBLKS) * 256 + threadIdx.x; }

    int m = idx >> 6, c4 = idx & 63;
    float4 v = ((const float4*)src)[idx];
    __align__(8) __nv_bfloat16 h[4];
    __align__(8) __nv_bfloat16 l[4];
    float f[4] = {v.x, v.y, v.z, v.w};
    #pragma unroll
    for (int j = 0; j < 4; j++) {
        h[j] = __float2bfloat16(f[j]);
        l[j] = __float2bfloat16(f[j] - __bfloat162float(h[j]));
    }
    __nv_bfloat16* base = dst + (size_t)m * KSPLIT + c4 * 4;
    if (bside) {
        *(uint2*)(base)       = *(uint2*)h;
        *(uint2*)(base + 256) = *(uint2*)h;
        *(uint2*)(base + 512) = *(uint2*)l;
    } else {
        *(uint2*)(base)       = *(uint2*)h;
        *(uint2*)(base + 256) = *(uint2*)l;
        *(uint2*)(base + 512) = *(uint2*)h;
    }
}

// ===========================================================================
// Attention v3 (round-8 proven) + occupancy floor of 5 CTAs/SM.
// Grid (NVERT, 2), block 128 (4 warps). Warp handles head h = by*4 + w.
// ===========================================================================
#define KPAD 36

__global__ __launch_bounds__(128, 5)
void attn_kernel(const int* __restrict__ which, const int* __restrict__ mask)
{
    __shared__ float k_s[4][32 * KPAD];  // [warp][key*36 + ch]  18432 B
    __shared__ float q_s[4][4 * HD];     // [warp][d*32 + ch]     2048 B
    __shared__ float p_s[4][4 * HD];     // [warp][d*32 + key]    2048 B

    const int n    = blockIdx.x;
    const int tid  = threadIdx.x;
    const int lane = tid & 31;
    const int w    = tid >> 5;
    const int h    = blockIdx.y * 4 + w;
    const unsigned full = 0xffffffffu;

    int wv = 0, mv = 0;
    if (lane < KNBR) {
        wv = which[n * KNBR + lane];
        mv = mask[n * KNBR + lane];
    }

    float vreg[32];
    #pragma unroll
    for (int r = 0; r < 32; r++) {
        int nb = __shfl_sync(full, wv, r >> 2);
        const float* rb = g_qkv + (size_t)(nb * 4 + (r & 3)) * 768 + h * HD + lane;
        k_s[w][r * KPAD + lane] = rb[DIM];
        vreg[r]                 = rb[2 * DIM];
    }
    #pragma unroll
    for (int d = 0; d < 4; d++)
        q_s[w][d * HD + lane] = g_qkv[(size_t)(n * 4 + d) * 768 + h * HD + lane];

    __syncwarp();
    const bool mk = __shfl_sync(full, mv, lane >> 2) != 0;

    float4 krow[8];
    #pragma unroll
    for (int i = 0; i < 8; i++)
        krow[i] = *(const float4*)&k_s[w][lane * KPAD + i * 4];

    float logits[4];
    #pragma unroll
    for (int d = 0; d < 4; d++) {
        float acc = 0.f;
        #pragma unroll
        for (int i = 0; i < 8; i++) {
            float4 q4 = *(const float4*)&q_s[w][d * HD + i * 4];
            acc = fmaf(krow[i].x, q4.x, acc);
            acc = fmaf(krow[i].y, q4.y, acc);
            acc = fmaf(krow[i].z, q4.z, acc);
            acc = fmaf(krow[i].w, q4.w, acc);
        }
        logits[d] = mk ? acc : -FLT_MAX;
    }

    #pragma unroll
    for (int d = 0; d < 4; d++) {
        float mx = logits[d];
        #pragma unroll
        for (int o = 16; o; o >>= 1) mx = fmaxf(mx, __shfl_xor_sync(full, mx, o));
        float e = mk ? __expf(logits[d] - mx) : 0.f;
        float sum = e;
        #pragma unroll
        for (int o = 16; o; o >>= 1) sum += __shfl_xor_sync(full, sum, o);
        p_s[w][d * HD + lane] = e / sum;
    }
    __syncwarp();

    #pragma unroll
    for (int d = 0; d < 4; d++) {
        float acc = 0.f;
        #pragma unroll
        for (int i = 0; i < 8; i++) {
            float4 p4 = *(const float4*)&p_s[w][d * HD + i * 4];
            acc = fmaf(p4.x, vreg[i * 4 + 0], acc);
            acc = fmaf(p4.y, vreg[i * 4 + 1], acc);
            acc = fmaf(p4.z, vreg[i * 4 + 2], acc);
            acc = fmaf(p4.w, vreg[i * 4 + 3], acc);
        }
        __nv_bfloat16 hi = __float2bfloat16(acc);
        __nv_bfloat16 lo = __float2bfloat16(acc - __bfloat162float(hi));
        __nv_bfloat16* yb = g_ybf + (size_t)(n * 4 + d) * KSPLIT + h * HD + lane;
        yb[0]   = hi;
        yb[256] = lo;
        yb[512] = hi;
    }
}

// ===========================================================================
extern "C" void kernel_launch(void* const* d_in, const int* in_sizes, int n_in,
                              void* d_out, int out_size)
{
    const float* x      = (const float*)d_in[0];
    const int*   which  = (const int*)d_in[1];
    const int*   mask   = (const int*)d_in[2];
    const float* qkv_w  = (const float*)d_in[3];
    const float* qkv_b  = (const float*)d_in[4];
    const float* proj_w = (const float*)d_in[5];
    const float* proj_b = (const float*)d_in[6];
    float*       out    = (float*)d_out;

    float *qkv_ptr = nullptr;
    __nv_bfloat16 *xbf = nullptr, *ybf = nullptr, *wqkv = nullptr, *wproj = nullptr;
    cudaGetSymbolAddress((void**)&qkv_ptr, g_qkv);
    cudaGetSymbolAddress((void**)&xbf,  g_xbf);
    cudaGetSymbolAddress((void**)&ybf,  g_ybf);
    cudaGetSymbolAddress((void**)&wqkv, g_wqkv);
    cudaGetSymbolAddress((void**)&wproj, g_wproj);

    const int M = MTOK;

    // 0) merged split-bf16 conversion (one launch for x, qkv_w, proj_w)
    conv_all<<<XBLKS + WQBLKS + WPBLKS, 256>>>(x, qkv_w, proj_w, xbf, wqkv, wproj);

    // 1) QKV GEMM (round-8 proven 128x128): q scaled
    {
        cudaFuncSetAttribute(gemm_mma<true>, cudaFuncAttributeMaxDynamicSharedMemorySize, GEMM_SMEM);
        dim3 grid(3 * DIM / 128, (M + 127) / 128);
        gemm_mma<true><<<grid, 256, GEMM_SMEM>>>(xbf, wqkv, qkv_b, qkv_ptr, M, 3 * DIM);
    }

    // 2) Attention (v3 + occupancy floor)
    {
        dim3 grid(NVERT, 2);
        attn_kernel<<<grid, 128>>>(which, mask);
    }

    // 3) Proj GEMM -> d_out
    {
        cudaFuncSetAttribute(gemm_mma<false>, cudaFuncAttributeMaxDynamicSharedMemorySize, GEMM_SMEM);
        dim3 grid(DIM / 128, (M + 127) / 128);
        gemm_mma<false><<<grid, 256, GEMM_SMEM>>>(ybf, wproj, proj_b, out, M, DIM);
    }
}

// round 16
// speedup vs baseline: 1.0558x; 1.0558x over previous
#include <cuda_runtime.h>
#include <cuda_bf16.h>
#include <cfloat>
#include <cstdint>

// Problem constants
#define NVERT 10242
#define DLEV  4
#define DIM   256
#define HEADS 8
#define HD    32
#define KNBR  8
#define MTOK  (NVERT * DLEV)          // 40968 tokens
#define KSPLIT 768                    // split-bf16 K: A=[hi|lo|hi] . B=[hi|hi|lo]
#define QSCALE 5.65685424949238f      // sqrt(32)

// Scratch (device globals; no allocation allowed)
__device__ float          g_qkv[(size_t)MTOK * 3 * DIM];     // [M,768] f32: q|k|v
__device__ __nv_bfloat16  g_xbf[(size_t)MTOK * KSPLIT];      // x split  [hi|lo|hi]
__device__ __nv_bfloat16  g_ybf[(size_t)MTOK * KSPLIT];      // y split  [hi|lo|hi]
__device__ __nv_bfloat16  g_wqkv[(size_t)(3*DIM) * KSPLIT];  // qkv_w split [hi|hi|lo]
__device__ __nv_bfloat16  g_wproj[(size_t)DIM * KSPLIT];     // proj_w split [hi|hi|lo]

// ===========================================================================
// helpers
// ===========================================================================
__device__ __forceinline__ uint32_t smem_u32(const void* p) {
    uint32_t a;
    asm("{ .reg .u64 t; cvta.to.shared.u64 t, %1; cvt.u32.u64 %0, t; }" : "=r"(a) : "l"(p));
    return a;
}
__device__ __forceinline__ void cp_async16(uint32_t saddr, const void* gptr, uint32_t bytes) {
    asm volatile("cp.async.cg.shared.global [%0], [%1], 16, %2;\n"
                 :: "r"(saddr), "l"(gptr), "r"(bytes));
}
__device__ __forceinline__ void cp_commit() {
    asm volatile("cp.async.commit_group;\n" ::: "memory");
}
template <int N>
__device__ __forceinline__ void cp_wait() {
    asm volatile("cp.async.wait_group %0;\n" :: "n"(N) : "memory");
}
__device__ __forceinline__ void ldsm_x4(uint32_t& r0, uint32_t& r1, uint32_t& r2, uint32_t& r3,
                                        uint32_t addr) {
    asm volatile("ldmatrix.sync.aligned.m8n8.x4.shared.b16 {%0,%1,%2,%3}, [%4];"
                 : "=r"(r0), "=r"(r1), "=r"(r2), "=r"(r3) : "r"(addr));
}
__device__ __forceinline__ void mma16816(float* d, const uint32_t* a, const uint32_t* b) {
    asm volatile(
        "mma.sync.aligned.m16n8k16.row.col.f32.bf16.bf16.f32 "
        "{%0,%1,%2,%3}, {%4,%5,%6,%7}, {%8,%9}, {%0,%1,%2,%3};"
        : "+f"(d[0]), "+f"(d[1]), "+f"(d[2]), "+f"(d[3])
        : "r"(a[0]), "r"(a[1]), "r"(a[2]), "r"(a[3]), "r"(b[0]), "r"(b[1]));
}

// ===========================================================================
// bf16 tensor-core GEMM (round-8 proven): 128x128 CTA tile, BK=64,
// 8 warps (2x4) of 64x32 warp tiles, cp.async double-buffered,
// XOR-swizzled smem, fused bias (+q scale).
// ===========================================================================
#define BK 64
#define KITERS (KSPLIT / BK)       // 12
#define TILE_BYTES (128 * BK * 2)  // 16384
#define BUF_BYTES  (2 * TILE_BYTES)
#define GEMM_SMEM  (2 * BUF_BYTES) // 65536

template <bool SCALEQ>
__global__ __launch_bounds__(256, 2)
void gemm_mma(const __nv_bfloat16* __restrict__ A, const __nv_bfloat16* __restrict__ B,
              const float* __restrict__ bias, float* __restrict__ C, int M, int N)
{
    extern __shared__ char sm[];
    const uint32_t smb = smem_u32(sm);
    const int tid  = threadIdx.x;
    const int lane = tid & 31;
    const int w    = tid >> 5;
    const int wm   = w >> 2;           // 0..1
    const int wn   = w & 3;            // 0..3
    const int bm   = blockIdx.y * 128;
    const int bn   = blockIdx.x * 128;

    const int a_r0  = wm * 64 + ((lane >> 3) & 1) * 8 + (lane & 7);
    const int a_khi = lane >> 4;
    const int b_r0  = wn * 32 + ((lane >> 4) & 1) * 8 + (lane & 7);
    const int b_khi = (lane >> 3) & 1;

    float acc[4][4][4];
    #pragma unroll
    for (int i = 0; i < 4; i++)
        #pragma unroll
        for (int j = 0; j < 4; j++)
            #pragma unroll
            for (int c = 0; c < 4; c++) acc[i][j][c] = 0.f;

    auto load_tile = [&](int buf, int it) {
        const int k0 = it * BK;
        const uint32_t sA = smb + buf * BUF_BYTES;
        const uint32_t sB = sA + TILE_BYTES;
        #pragma unroll
        for (int i = 0; i < 4; i++) {
            int e = tid + i * 256;
            int r = e >> 3, u = e & 7;
            int gr = bm + r;
            bool ok = gr < M;
            const __nv_bfloat16* ga = A + (size_t)(ok ? gr : 0) * KSPLIT + k0 + u * 8;
            cp_async16(sA + r * 128 + ((u ^ (r & 7)) << 4), ga, ok ? 16u : 0u);
            const __nv_bfloat16* gb = B + (size_t)(bn + r) * KSPLIT + k0 + u * 8;
            cp_async16(sB + r * 128 + ((u ^ (r & 7)) << 4), gb, 16u);
        }
        cp_commit();
    };

    auto compute = [&](int buf) {
        const uint32_t sA = smb + buf * BUF_BYTES;
        const uint32_t sB = sA + TILE_BYTES;
        #pragma unroll
        for (int ks = 0; ks < BK / 16; ks++) {
            uint32_t a[4][4];
            #pragma unroll
            for (int mf = 0; mf < 4; mf++) {
                int row = a_r0 + mf * 16;
                int ku  = ks * 2 + a_khi;
                ldsm_x4(a[mf][0], a[mf][1], a[mf][2], a[mf][3],
                        sA + row * 128 + ((ku ^ (row & 7)) << 4));
            }
            uint32_t b[4][2];
            #pragma unroll
            for (int np = 0; np < 2; np++) {
                int row = b_r0 + np * 16;
                int ku  = ks * 2 + b_khi;
                uint32_t r0, r1, r2, r3;
                ldsm_x4(r0, r1, r2, r3, sB + row * 128 + ((ku ^ (row & 7)) << 4));
                b[np * 2 + 0][0] = r0; b[np * 2 + 0][1] = r1;
                b[np * 2 + 1][0] = r2; b[np * 2 + 1][1] = r3;
            }
            #pragma unroll
            for (int mf = 0; mf < 4; mf++)
                #pragma unroll
                for (int nf = 0; nf < 4; nf++)
                    mma16816(acc[mf][nf], a[mf], b[nf]);
        }
    };

    load_tile(0, 0);
    #pragma unroll 1
    for (int it = 0; it < KITERS; it++) {
        if (it + 1 < KITERS) { load_tile((it + 1) & 1, it + 1); cp_wait<1>(); }
        else                 { cp_wait<0>(); }
        __syncthreads();
        compute(it & 1);
        __syncthreads();
    }

    const int gn_base = bn + wn * 32 + (lane & 3) * 2;
    #pragma unroll
    for (int mf = 0; mf < 4; mf++) {
        #pragma unroll
        for (int half = 0; half < 2; half++) {
            int gm = bm + wm * 64 + mf * 16 + (lane >> 2) + half * 8;
            if (gm >= M) continue;
            #pragma unroll
            for (int nf = 0; nf < 4; nf++) {
                int gn = gn_base + nf * 8;
                float v0 = acc[mf][nf][half * 2 + 0] + bias[gn];
                float v1 = acc[mf][nf][half * 2 + 1] + bias[gn + 1];
                if (SCALEQ && gn < DIM) { v0 *= QSCALE; v1 *= QSCALE; }
                *(float2*)(C + (size_t)gm * N + gn) = make_float2(v0, v1);
            }
        }
    }
}

// ===========================================================================
// Merged fp32 -> split-bf16 conversion for all three tensors in ONE launch.
//   x      (A-side): [hi | lo | hi]   blocks [0, 10242)
//   qkv_w  (B-side): [hi | hi | lo]   blocks [10242, 10434)
//   proj_w (B-side): [hi | hi | lo]   blocks [10434, 10498)
// ===========================================================================
#define XBLKS  (MTOK / 4)            // 10242
#define WQBLKS (3 * DIM / 4)         // 192
#define WPBLKS (DIM / 4)             // 64

__global__ void conv_all(const float* __restrict__ x,
                         const float* __restrict__ wq,
                         const float* __restrict__ wp,
                         __nv_bfloat16* __restrict__ xd,
                         __nv_bfloat16* __restrict__ wqd,
                         __nv_bfloat16* __restrict__ wpd)
{
    int b = blockIdx.x;
    const float* src;
    __nv_bfloat16* dst;
    bool bside;
    int idx;
    if (b < XBLKS)                 { src = x;  dst = xd;  bside = false; idx = b * 256 + threadIdx.x; }
    else if (b < XBLKS + WQBLKS)   { src = wq; dst = wqd; bside = true;  idx = (b - XBLKS) * 256 + threadIdx.x; }
    else                           { src = wp; dst = wpd; bside = true;  idx = (b - XBLKS - WQBLKS) * 256 + threadIdx.x; }

    int m = idx >> 6, c4 = idx & 63;
    float4 v = ((const float4*)src)[idx];
    __align__(8) __nv_bfloat16 h[4];
    __align__(8) __nv_bfloat16 l[4];
    float f[4] = {v.x, v.y, v.z, v.w};
    #pragma unroll
    for (int j = 0; j < 4; j++) {
        h[j] = __float2bfloat16(f[j]);
        l[j] = __float2bfloat16(f[j] - __bfloat162float(h[j]));
    }
    __nv_bfloat16* base = dst + (size_t)m * KSPLIT + c4 * 4;
    if (bside) {
        *(uint2*)(base)       = *(uint2*)h;
        *(uint2*)(base + 256) = *(uint2*)h;
        *(uint2*)(base + 512) = *(uint2*)l;
    } else {
        *(uint2*)(base)       = *(uint2*)h;
        *(uint2*)(base + 256) = *(uint2*)l;
        *(uint2*)(base + 512) = *(uint2*)h;
    }
}

// ===========================================================================
// Attention v3 (round-8 proven, NO occupancy cap): warp-synchronous,
// shfl-free inner loops. Grid (NVERT, 2), block 128 (4 warps).
// Warp handles head h = by*4 + w.
// ===========================================================================
#define KPAD 36

__global__ void attn_kernel(const int* __restrict__ which, const int* __restrict__ mask)
{
    __shared__ float k_s[4][32 * KPAD];  // [warp][key*36 + ch]  18432 B
    __shared__ float q_s[4][4 * HD];     // [warp][d*32 + ch]     2048 B
    __shared__ float p_s[4][4 * HD];     // [warp][d*32 + key]    2048 B

    const int n    = blockIdx.x;
    const int tid  = threadIdx.x;
    const int lane = tid & 31;
    const int w    = tid >> 5;
    const int h    = blockIdx.y * 4 + w;
    const unsigned full = 0xffffffffu;

    int wv = 0, mv = 0;
    if (lane < KNBR) {
        wv = which[n * KNBR + lane];
        mv = mask[n * KNBR + lane];
    }

    float vreg[32];
    #pragma unroll
    for (int r = 0; r < 32; r++) {
        int nb = __shfl_sync(full, wv, r >> 2);
        const float* rb = g_qkv + (size_t)(nb * 4 + (r & 3)) * 768 + h * HD + lane;
        k_s[w][r * KPAD + lane] = rb[DIM];
        vreg[r]                 = rb[2 * DIM];
    }
    #pragma unroll
    for (int d = 0; d < 4; d++)
        q_s[w][d * HD + lane] = g_qkv[(size_t)(n * 4 + d) * 768 + h * HD + lane];

    __syncwarp();
    const bool mk = __shfl_sync(full, mv, lane >> 2) != 0;

    float4 krow[8];
    #pragma unroll
    for (int i = 0; i < 8; i++)
        krow[i] = *(const float4*)&k_s[w][lane * KPAD + i * 4];

    float logits[4];
    #pragma unroll
    for (int d = 0; d < 4; d++) {
        float acc = 0.f;
        #pragma unroll
        for (int i = 0; i < 8; i++) {
            float4 q4 = *(const float4*)&q_s[w][d * HD + i * 4];
            acc = fmaf(krow[i].x, q4.x, acc);
            acc = fmaf(krow[i].y, q4.y, acc);
            acc = fmaf(krow[i].z, q4.z, acc);
            acc = fmaf(krow[i].w, q4.w, acc);
        }
        logits[d] = mk ? acc : -FLT_MAX;
    }

    #pragma unroll
    for (int d = 0; d < 4; d++) {
        float mx = logits[d];
        #pragma unroll
        for (int o = 16; o; o >>= 1) mx = fmaxf(mx, __shfl_xor_sync(full, mx, o));
        float e = mk ? __expf(logits[d] - mx) : 0.f;
        float sum = e;
        #pragma unroll
        for (int o = 16; o; o >>= 1) sum += __shfl_xor_sync(full, sum, o);
        p_s[w][d * HD + lane] = e / sum;
    }
    __syncwarp();

    #pragma unroll
    for (int d = 0; d < 4; d++) {
        float acc = 0.f;
        #pragma unroll
        for (int i = 0; i < 8; i++) {
            float4 p4 = *(const float4*)&p_s[w][d * HD + i * 4];
            acc = fmaf(p4.x, vreg[i * 4 + 0], acc);
            acc = fmaf(p4.y, vreg[i * 4 + 1], acc);
            acc = fmaf(p4.z, vreg[i * 4 + 2], acc);
            acc = fmaf(p4.w, vreg[i * 4 + 3], acc);
        }
        __nv_bfloat16 hi = __float2bfloat16(acc);
        __nv_bfloat16 lo = __float2bfloat16(acc - __bfloat162float(hi));
        __nv_bfloat16* yb = g_ybf + (size_t)(n * 4 + d) * KSPLIT + h * HD + lane;
        yb[0]   = hi;
        yb[256] = lo;
        yb[512] = hi;
    }
}

// ===========================================================================
extern "C" void kernel_launch(void* const* d_in, const int* in_sizes, int n_in,
                              void* d_out, int out_size)
{
    const float* x      = (const float*)d_in[0];
    const int*   which  = (const int*)d_in[1];
    const int*   mask   = (const int*)d_in[2];
    const float* qkv_w  = (const float*)d_in[3];
    const float* qkv_b  = (const float*)d_in[4];
    const float* proj_w = (const float*)d_in[5];
    const float* proj_b = (const float*)d_in[6];
    float*       out    = (float*)d_out;

    float *qkv_ptr = nullptr;
    __nv_bfloat16 *xbf = nullptr, *ybf = nullptr, *wqkv = nullptr, *wproj = nullptr;
    cudaGetSymbolAddress((void**)&qkv_ptr, g_qkv);
    cudaGetSymbolAddress((void**)&xbf,  g_xbf);
    cudaGetSymbolAddress((void**)&ybf,  g_ybf);
    cudaGetSymbolAddress((void**)&wqkv, g_wqkv);
    cudaGetSymbolAddress((void**)&wproj, g_wproj);

    const int M = MTOK;

    // 0) merged split-bf16 conversion (one launch for x, qkv_w, proj_w)
    conv_all<<<XBLKS + WQBLKS + WPBLKS, 256>>>(x, qkv_w, proj_w, xbf, wqkv, wproj);

    // 1) QKV GEMM (round-8 proven 128x128): q scaled
    {
        cudaFuncSetAttribute(gemm_mma<true>, cudaFuncAttributeMaxDynamicSharedMemorySize, GEMM_SMEM);
        dim3 grid(3 * DIM / 128, (M + 127) / 128);
        gemm_mma<true><<<grid, 256, GEMM_SMEM>>>(xbf, wqkv, qkv_b, qkv_ptr, M, 3 * DIM);
    }

    // 2) Attention (v3, no occupancy cap)
    {
        dim3 grid(NVERT, 2);
        attn_kernel<<<grid, 128>>>(which, mask);
    }

    // 3) Proj GEMM -> d_out
    {
        cudaFuncSetAttribute(gemm_mma<false>, cudaFuncAttributeMaxDynamicSharedMemorySize, GEMM_SMEM);
        dim3 grid(DIM / 128, (M + 127) / 128);
        gemm_mma<false><<<grid, 256, GEMM_SMEM>>>(ybf, wproj, proj_b, out, M, DIM);
    }
}